// round 4
// baseline (speedup 1.0000x reference)
#include <cuda_runtime.h>
#include <cstdint>

// ---------------- problem constants ----------------
#define T_TOK   16384
#define D_DIM   2048
#define E_EXP   64
#define AUX_W   0.01f

#define BM      128
#define BK      32
#define THREADS 256
#define NCTA    (T_TOK / BM)      // 128
#define GCHUNK  32                // chunks per k-group (2 groups x 32 = 64)

// packed tile layout: row stride = 4 k8-groups * 4 slots * 16B + 16B pad = 272 B (68 words)
// slot j of k8-group holds {hi(k8*8+j), lo(k8*8+j), hi(k8*8+j+4), lo(k8*8+j+4)}
#define ROW_W   68
#define A_WORDS (128 * ROW_W)                 // 8704
#define B_WORDS (64 * ROW_W)                  // 4352
#define STG_W   (A_WORDS + B_WORDS)           // 13056 words = 52224 B
#define DYN_SMEM (4 * STG_W * 4)              // 208896 B (2 groups x 2 stages)
#define LPAD    68

// ---------------- global scratch ----------------
__device__ float    g_psum[NCTA * E_EXP];
__device__ float    g_pcnt[NCTA * E_EXP];
__device__ unsigned g_done = 0;

// ---------------- helpers ----------------
__device__ __forceinline__ uint32_t smem_u32(const void* p) {
    uint32_t a;
    asm("{ .reg .u64 t; cvta.to.shared.u64 t, %1; cvt.u32.u64 %0, t; }" : "=r"(a) : "l"(p));
    return a;
}
__device__ __forceinline__ void cvt_hilo(float x, uint32_t& hi, uint32_t& lo) {
    uint32_t h;
    asm("cvt.rna.tf32.f32 %0, %1;" : "=r"(h) : "f"(x));
    float r = x - __uint_as_float(h);
    uint32_t l;
    asm("cvt.rna.tf32.f32 %0, %1;" : "=r"(l) : "f"(r));
    hi = h; lo = l;
}
__device__ __forceinline__ void sts64(uint32_t addr, uint32_t a, uint32_t b) {
    asm volatile("st.shared.v2.b32 [%0], {%1, %2};" :: "r"(addr), "r"(a), "r"(b) : "memory");
}
__device__ __forceinline__ uint4 lds128(uint32_t addr) {
    uint4 r;
    asm volatile("ld.shared.v4.b32 {%0,%1,%2,%3}, [%4];"
        : "=r"(r.x), "=r"(r.y), "=r"(r.z), "=r"(r.w) : "r"(addr));
    return r;
}
#define MMA_TF32(c, a, b) \
    asm volatile("mma.sync.aligned.m16n8k8.row.col.f32.tf32.tf32.f32 " \
        "{%0,%1,%2,%3}, {%4,%5,%6,%7}, {%8,%9}, {%0,%1,%2,%3};" \
        : "+f"((c)[0]), "+f"((c)[1]), "+f"((c)[2]), "+f"((c)[3]) \
        : "r"((a)[0]), "r"((a)[1]), "r"((a)[2]), "r"((a)[3]), "r"((b)[0]), "r"((b)[1]))

extern __shared__ __align__(16) float Sf[];

__global__ __launch_bounds__(THREADS, 1) void router_kernel(
    const float* __restrict__ X,   // [T_TOK, D]
    const float* __restrict__ W,   // [E, D]
    float* __restrict__ out)       // [2T idx | 2T w | 1 aux]
{
    __shared__ int   sCnt[E_EXP];
    __shared__ float sRed[E_EXP];
    __shared__ unsigned s_last;

    const int tid  = threadIdx.x;
    const int lane = tid & 31;
    const int wrp  = tid >> 5;
    const int quad = lane >> 2;
    const int qt   = lane & 3;
    const int g    = wrp >> 2;       // k-group: 0 -> chunks [0,32), 1 -> [32,64)
    const int wg   = wrp & 3;        // warp-in-group: rows [wg*32, +32), all 64 cols
    const int gt   = tid & 127;      // thread index within group
    const int bid  = blockIdx.x;
    const int m0   = bid * BM;

    if (tid < E_EXP) sCnt[tid] = 0;

    const float* Xp = X + (size_t)m0 * D_DIM;
    const uint32_t sb = smem_u32(Sf);
    uint32_t stA[2], stB[2];
#pragma unroll
    for (int s = 0; s < 2; s++) {
        stA[s] = sb + (uint32_t)((g * 2 + s) * STG_W) * 4u;
        stB[s] = stA[s] + A_WORDS * 4u;
    }

    // per-thread load slots (within group: 128 threads)
    int xr[8], xc[8], wr[4], wc[4];
#pragma unroll
    for (int r = 0; r < 8; r++) { int s = gt + r * 128; xr[r] = s >> 3; xc[r] = s & 7; }
#pragma unroll
    for (int r = 0; r < 4; r++) { int s = gt + r * 128; wr[r] = s >> 3; wc[r] = s & 7; }

    float4 xv[8], wv[4];

    auto load_chunk = [&](int gc) {
        const int kb = gc * BK;
#pragma unroll
        for (int r = 0; r < 8; r++) xv[r] = *(const float4*)(Xp + (size_t)xr[r] * D_DIM + kb + xc[r] * 4);
#pragma unroll
        for (int r = 0; r < 4; r++) wv[r] = *(const float4*)(W  + (size_t)wr[r] * D_DIM + kb + wc[r] * 4);
    };
    auto store_chunk = [&](int s) {
#pragma unroll
        for (int r = 0; r < 8; r++) {
            uint32_t base = stA[s] + (uint32_t)xr[r] * 272u + (uint32_t)(xc[r] >> 1) * 64u + (uint32_t)(xc[r] & 1) * 8u;
            const float* v = (const float*)&xv[r];
#pragma unroll
            for (int j = 0; j < 4; j++) {
                uint32_t h, l; cvt_hilo(v[j], h, l);
                sts64(base + (uint32_t)j * 16u, h, l);
            }
        }
#pragma unroll
        for (int r = 0; r < 4; r++) {
            uint32_t base = stB[s] + (uint32_t)wr[r] * 272u + (uint32_t)(wc[r] >> 1) * 64u + (uint32_t)(wc[r] & 1) * 8u;
            const float* v = (const float*)&wv[r];
#pragma unroll
            for (int j = 0; j < 4; j++) {
                uint32_t h, l; cvt_hilo(v[j], h, l);
                sts64(base + (uint32_t)j * 16u, h, l);
            }
        }
    };

    float acc[2][8][4];
#pragma unroll
    for (int mi = 0; mi < 2; mi++)
#pragma unroll
        for (int ni = 0; ni < 8; ni++)
#pragma unroll
            for (int r = 0; r < 4; r++) acc[mi][ni][r] = 0.0f;

    // prologue
    load_chunk(g * GCHUNK);
    store_chunk(0);
    __syncthreads();

    const uint32_t aRowOff = (uint32_t)(wg * 32 + quad) * 272u;
    const uint32_t qtOff   = (uint32_t)qt * 16u;

#pragma unroll 1
    for (int c = 0; c < GCHUNK; c++) {
        if (c + 1 < GCHUNK) load_chunk(g * GCHUNK + c + 1);   // in flight during MMA

        const uint32_t Ab = stA[c & 1], Bb = stB[c & 1];
#pragma unroll
        for (int k8 = 0; k8 < 4; k8++) {
            const uint32_t off = (uint32_t)k8 * 64u + qtOff;
            uint4 La0 = lds128(Ab + aRowOff + off);
            uint4 La1 = lds128(Ab + aRowOff + 8u * 272u + off);
            uint4 La2 = lds128(Ab + aRowOff + 16u * 272u + off);
            uint4 La3 = lds128(Ab + aRowOff + 24u * 272u + off);
            uint32_t ahi[2][4], alo[2][4];
            ahi[0][0] = La0.x; ahi[0][1] = La1.x; ahi[0][2] = La0.z; ahi[0][3] = La1.z;
            alo[0][0] = La0.y; alo[0][1] = La1.y; alo[0][2] = La0.w; alo[0][3] = La1.w;
            ahi[1][0] = La2.x; ahi[1][1] = La3.x; ahi[1][2] = La2.z; ahi[1][3] = La3.z;
            alo[1][0] = La2.y; alo[1][1] = La3.y; alo[1][2] = La2.w; alo[1][3] = La3.w;

            uint32_t bhi[8][2], blo[8][2];
#pragma unroll
            for (int ni = 0; ni < 8; ni++) {
                uint4 Lb = lds128(Bb + (uint32_t)(ni * 8 + quad) * 272u + off);
                bhi[ni][0] = Lb.x; bhi[ni][1] = Lb.z;
                blo[ni][0] = Lb.y; blo[ni][1] = Lb.w;
            }
#pragma unroll
            for (int mi = 0; mi < 2; mi++)
#pragma unroll
                for (int ni = 0; ni < 8; ni++) MMA_TF32(acc[mi][ni], ahi[mi], bhi[ni]);
#pragma unroll
            for (int mi = 0; mi < 2; mi++)
#pragma unroll
                for (int ni = 0; ni < 8; ni++) MMA_TF32(acc[mi][ni], ahi[mi], blo[ni]);
#pragma unroll
            for (int mi = 0; mi < 2; mi++)
#pragma unroll
                for (int ni = 0; ni < 8; ni++) MMA_TF32(acc[mi][ni], alo[mi], bhi[ni]);
        }
        if (c + 1 < GCHUNK) store_chunk((c + 1) & 1);
        __syncthreads();
    }

    // ---------- combine the two k-groups' partial logits into Sf[128][68] ----------
    if (g == 1) {
#pragma unroll
        for (int mi = 0; mi < 2; mi++)
#pragma unroll
            for (int ni = 0; ni < 8; ni++) {
                int row = wg * 32 + mi * 16 + quad;
                int col = ni * 8 + 2 * qt;
                *(float2*)&Sf[row * LPAD + col]       = make_float2(acc[mi][ni][0], acc[mi][ni][1]);
                *(float2*)&Sf[(row + 8) * LPAD + col] = make_float2(acc[mi][ni][2], acc[mi][ni][3]);
            }
    }
    __syncthreads();
    if (g == 0) {
#pragma unroll
        for (int mi = 0; mi < 2; mi++)
#pragma unroll
            for (int ni = 0; ni < 8; ni++) {
                int row = wg * 32 + mi * 16 + quad;
                int col = ni * 8 + 2 * qt;
                float2 p0 = *(float2*)&Sf[row * LPAD + col];
                float2 p1 = *(float2*)&Sf[(row + 8) * LPAD + col];
                *(float2*)&Sf[row * LPAD + col]       = make_float2(p0.x + acc[mi][ni][0], p0.y + acc[mi][ni][1]);
                *(float2*)&Sf[(row + 8) * LPAD + col] = make_float2(p1.x + acc[mi][ni][2], p1.y + acc[mi][ni][3]);
            }
    }
    __syncthreads();

    // ---------- per-token epilogue ----------
    const bool act = tid < BM;
    float v[E_EXP];
    float l1 = -1e30f, l2 = -1e30f, inv = 0.0f;
    int   i1 = 0, i2 = 0;
    if (act) {
        const float* row = &Sf[tid * LPAD];
#pragma unroll
        for (int j = 0; j < E_EXP / 4; j++) {
            float4 q = *(const float4*)&row[4 * j];
            v[4 * j] = q.x; v[4 * j + 1] = q.y; v[4 * j + 2] = q.z; v[4 * j + 3] = q.w;
        }
#pragma unroll
        for (int e = 0; e < E_EXP; e++) {
            float x = v[e];
            if (x > l1)      { l2 = l1; i2 = i1; l1 = x; i1 = e; }
            else if (x > l2) { l2 = x;  i2 = e; }
        }
        float ssum = 0.0f;
#pragma unroll
        for (int e = 0; e < E_EXP; e++) { float p = __expf(v[e] - l1); ssum += p; v[e] = p; }
        inv = 1.0f / ssum;
    }
    __syncthreads();   // all logit reads done before packed-prob overwrite
    if (act) {
#pragma unroll
        for (int j = 0; j < E_EXP / 4; j++) {
            float4 q = make_float4(v[4 * j] * inv, v[4 * j + 1] * inv, v[4 * j + 2] * inv, v[4 * j + 3] * inv);
            *(float4*)&Sf[tid * E_EXP + 4 * j] = q;
        }
        float e2 = __expf(l2 - l1);
        float dn = 1.0f / (1.0f + e2);
        int gm = m0 + tid;
        out[2 * gm + 0] = (float)i1;
        out[2 * gm + 1] = (float)i2;
        out[2 * T_TOK + 2 * gm + 0] = dn;
        out[2 * T_TOK + 2 * gm + 1] = e2 * dn;
        atomicAdd(&sCnt[i1], 1);
    }
    __syncthreads();

    // ---------- per-expert partials ----------
    if (tid < E_EXP) {
        float s = 0.0f;
#pragma unroll 8
        for (int m = 0; m < BM; m++) s += Sf[m * E_EXP + tid];
        g_psum[bid * E_EXP + tid] = s;
        g_pcnt[bid * E_EXP + tid] = (float)sCnt[tid];
    }
    __threadfence();
    __syncthreads();

    if (tid == 0) s_last = (atomicInc(&g_done, NCTA - 1) == NCTA - 1) ? 1u : 0u;
    __syncthreads();

    if (s_last) {
        __threadfence();
        if (tid < E_EXP) {
            float a = 0.0f, cn = 0.0f;
#pragma unroll 8
            for (int b = 0; b < NCTA; b++) {
                a  += __ldcg(&g_psum[b * E_EXP + tid]);
                cn += __ldcg(&g_pcnt[b * E_EXP + tid]);
            }
            float invT = 1.0f / (float)T_TOK;
            sRed[tid] = (cn * invT) * (a * invT);
        }
        __syncthreads();
        if (tid < 32) {
            float vv = sRed[tid] + sRed[tid + 32];
#pragma unroll
            for (int o = 16; o > 0; o >>= 1) vv += __shfl_xor_sync(0xFFFFFFFF, vv, o);
            if (tid == 0) out[4 * T_TOK] = (float)E_EXP * AUX_W * vv;
        }
    }
}

extern "C" void kernel_launch(void* const* d_in, const int* in_sizes, int n_in,
                              void* d_out, int out_size) {
    const float* X = (const float*)d_in[0];
    const float* W = (const float*)d_in[1];
    float* out = (float*)d_out;

    cudaFuncSetAttribute(router_kernel, cudaFuncAttributeMaxDynamicSharedMemorySize, DYN_SMEM);
    router_kernel<<<NCTA, THREADS, DYN_SMEM>>>(X, W, out);
}

// round 7
// speedup vs baseline: 1.4054x; 1.4054x over previous
#include <cuda_runtime.h>
#include <cstdint>

// ---------------- problem constants ----------------
#define T_TOK   16384
#define D_DIM   2048
#define E_EXP   64
#define AUX_W   0.01f

#define BM      128
#define BK      32
#define NCHUNK  (D_DIM / BK)      // 64
#define THREADS 256
#define NCTA    (T_TOK / BM)      // 128
#define LPAD    68

// smem stage layout (bytes): A rows stride 36 floats = 144 B
#define AHI_OFF 0
#define ALO_OFF 18432
#define BHI_OFF 36864
#define BLO_OFF 46080
#define STG_B   55296
#define DYN_SMEM (2 * STG_B)      // 110592 B

// ---------------- global scratch ----------------
__device__ uint32_t g_Whi[E_EXP * D_DIM];
__device__ uint32_t g_Wlo[E_EXP * D_DIM];
__device__ float    g_psum[NCTA * E_EXP];
__device__ float    g_pcnt[NCTA * E_EXP];
__device__ unsigned g_done = 0;

// ---------------- helpers ----------------
__device__ __forceinline__ uint32_t smem_u32(const void* p) {
    uint32_t a;
    asm("{ .reg .u64 t; cvta.to.shared.u64 t, %1; cvt.u32.u64 %0, t; }" : "=r"(a) : "l"(p));
    return a;
}
__device__ __forceinline__ void cvt_hilo(float x, uint32_t& hi, uint32_t& lo) {
    uint32_t h;
    asm("cvt.rna.tf32.f32 %0, %1;" : "=r"(h) : "f"(x));
    float r = x - __uint_as_float(h);
    uint32_t l;
    asm("cvt.rna.tf32.f32 %0, %1;" : "=r"(l) : "f"(r));
    hi = h; lo = l;
}
__device__ __forceinline__ void sts128u(uint32_t addr, uint32_t a, uint32_t b, uint32_t c, uint32_t d) {
    asm volatile("st.shared.v4.b32 [%0], {%1,%2,%3,%4};" :: "r"(addr), "r"(a), "r"(b), "r"(c), "r"(d) : "memory");
}
__device__ __forceinline__ uint32_t lds32(uint32_t addr) {
    uint32_t r;
    asm volatile("ld.shared.b32 %0, [%1];" : "=r"(r) : "r"(addr));
    return r;
}
#define CP_ASYNC16(saddr, gptr) \
    asm volatile("cp.async.cg.shared.global [%0], [%1], 16;" :: "r"(saddr), "l"(gptr) : "memory")
#define CP_COMMIT() asm volatile("cp.async.commit_group;" ::: "memory")
#define CP_WAIT0()  asm volatile("cp.async.wait_group 0;" ::: "memory")

#define MMA_TF32(c, a, b) \
    asm volatile("mma.sync.aligned.m16n8k8.row.col.f32.tf32.tf32.f32 " \
        "{%0,%1,%2,%3}, {%4,%5,%6,%7}, {%8,%9}, {%0,%1,%2,%3};" \
        : "+f"((c)[0]), "+f"((c)[1]), "+f"((c)[2]), "+f"((c)[3]) \
        : "r"((a)[0]), "r"((a)[1]), "r"((a)[2]), "r"((a)[3]), "r"((b)[0]), "r"((b)[1]))

// ---------------- W precompute ----------------
__global__ __launch_bounds__(256) void prep_kernel(const float* __restrict__ W) {
    int i = blockIdx.x * 256 + threadIdx.x;      // float4 index, 32768 total
    float4 v = ((const float4*)W)[i];
    uint32_t h0, l0, h1, l1, h2, l2, h3, l3;
    cvt_hilo(v.x, h0, l0); cvt_hilo(v.y, h1, l1);
    cvt_hilo(v.z, h2, l2); cvt_hilo(v.w, h3, l3);
    ((uint4*)g_Whi)[i] = make_uint4(h0, h1, h2, h3);
    ((uint4*)g_Wlo)[i] = make_uint4(l0, l1, l2, l3);
}

// ---------------- router ----------------
extern __shared__ __align__(16) float Sf[];

__global__ __launch_bounds__(THREADS, 1) void router_kernel(
    const float* __restrict__ X,
    const float* __restrict__ W,
    float* __restrict__ out)
{
    __shared__ int   sCnt[E_EXP];
    __shared__ float sRed[E_EXP];
    __shared__ unsigned s_last;

    const int tid   = threadIdx.x;
    const int lane  = tid & 31;
    const int wrp   = tid >> 5;
    const int warpM = wrp >> 1;       // 0..3
    const int warpN = wrp & 1;        // 0..1
    const int quad  = lane >> 2;
    const int qt    = lane & 3;
    const int bid   = blockIdx.x;
    const int m0    = bid * BM;

    if (tid < E_EXP) sCnt[tid] = 0;

    const float* Xp = X + (size_t)m0 * D_DIM;
    const uint32_t sb = smem_u32(Sf);

    // A slots: idx = tid + r*256 (r<4): row = idx>>3, c4 = idx&7
    int ar[4], ac[4];
#pragma unroll
    for (int r = 0; r < 4; r++) { int s = tid + r * THREADS; ar[r] = s >> 3; ac[r] = s & 7; }

    float4 xv[4];
    auto ldgx = [&](int i) {
        const int kt = i * BK;
#pragma unroll
        for (int r = 0; r < 4; r++) xv[r] = *(const float4*)(Xp + (size_t)ar[r] * D_DIM + kt + ac[r] * 4);
    };
    auto stsa = [&](int s) {
        const uint32_t st = sb + (uint32_t)s * STG_B;
#pragma unroll
        for (int r = 0; r < 4; r++) {
            uint32_t addr = st + (uint32_t)ar[r] * 144u + (uint32_t)ac[r] * 16u;
            uint32_t h0, l0, h1, l1, h2, l2, h3, l3;
            cvt_hilo(xv[r].x, h0, l0); cvt_hilo(xv[r].y, h1, l1);
            cvt_hilo(xv[r].z, h2, l2); cvt_hilo(xv[r].w, h3, l3);
            sts128u(addr + AHI_OFF, h0, h1, h2, h3);
            sts128u(addr + ALO_OFF, l0, l1, l2, l3);
        }
    };
    auto cpb = [&](int i, int s) {
        const int kt = i * BK;
        const uint32_t st = sb + (uint32_t)s * STG_B;
#pragma unroll
        for (int r = 0; r < 4; r++) {
            int idx = tid + r * THREADS;          // 0..1023
            int a   = idx >> 9;                   // 0: hi, 1: lo
            int j   = idx & 511;
            int row = j >> 3, c4 = j & 7;
            const uint32_t* src = (a ? g_Wlo : g_Whi) + (size_t)row * D_DIM + kt + c4 * 4;
            uint32_t dst = st + (a ? BLO_OFF : BHI_OFF) + (uint32_t)row * 144u + (uint32_t)c4 * 16u;
            CP_ASYNC16(dst, src);
        }
        CP_COMMIT();
    };

    float acc[2][4][4];
#pragma unroll
    for (int mi = 0; mi < 2; mi++)
#pragma unroll
        for (int ni = 0; ni < 4; ni++)
#pragma unroll
            for (int r = 0; r < 4; r++) acc[mi][ni][r] = 0.0f;

    // ---- prologue ----
    ldgx(0);
    stsa(0);
    cpb(0, 0);
    ldgx(1);
    CP_WAIT0();
    __syncthreads();

    const uint32_t aRow0 = (uint32_t)(warpM * 32 + quad) * 144u;
    const uint32_t bRow0 = (uint32_t)(warpN * 32 + quad) * 144u;

    uint32_t ahi[2][2][4], alo[2][2][4], bhi[2][4][2], blo[2][4][2];

    auto ldfrag = [&](uint32_t st, int k8, int buf) {
        const uint32_t off = (uint32_t)(k8 * 8 + qt) * 4u;
#pragma unroll
        for (int mi = 0; mi < 2; mi++) {
            uint32_t base = st + aRow0 + (uint32_t)(mi * 16) * 144u + off;
            ahi[buf][mi][0] = lds32(base + AHI_OFF);
            ahi[buf][mi][1] = lds32(base + AHI_OFF + 8u * 144u);
            ahi[buf][mi][2] = lds32(base + AHI_OFF + 16u);
            ahi[buf][mi][3] = lds32(base + AHI_OFF + 8u * 144u + 16u);
            alo[buf][mi][0] = lds32(base + ALO_OFF);
            alo[buf][mi][1] = lds32(base + ALO_OFF + 8u * 144u);
            alo[buf][mi][2] = lds32(base + ALO_OFF + 16u);
            alo[buf][mi][3] = lds32(base + ALO_OFF + 8u * 144u + 16u);
        }
#pragma unroll
        for (int ni = 0; ni < 4; ni++) {
            uint32_t base = st + bRow0 + (uint32_t)(ni * 8) * 144u + off;
            bhi[buf][ni][0] = lds32(base + BHI_OFF);
            bhi[buf][ni][1] = lds32(base + BHI_OFF + 16u);
            blo[buf][ni][0] = lds32(base + BLO_OFF);
            blo[buf][ni][1] = lds32(base + BLO_OFF + 16u);
        }
    };

#pragma unroll 1
    for (int i = 0; i < NCHUNK; i++) {
        const int s = i & 1;
        const uint32_t st = sb + (uint32_t)s * STG_B;

        // producer for chunk i+1 / i+2
        if (i + 1 < NCHUNK) { cpb(i + 1, s ^ 1); stsa(s ^ 1); }
        if (i + 2 < NCHUNK) ldgx(i + 2);

        // consumer: software-pipelined fragments
        ldfrag(st, 0, 0);
#pragma unroll
        for (int k8 = 0; k8 < 4; k8++) {
            const int cur = k8 & 1;
            if (k8 < 3) ldfrag(st, k8 + 1, cur ^ 1);
#pragma unroll
            for (int mi = 0; mi < 2; mi++)
#pragma unroll
                for (int ni = 0; ni < 4; ni++) MMA_TF32(acc[mi][ni], ahi[cur][mi], bhi[cur][ni]);
#pragma unroll
            for (int mi = 0; mi < 2; mi++)
#pragma unroll
                for (int ni = 0; ni < 4; ni++) MMA_TF32(acc[mi][ni], ahi[cur][mi], blo[cur][ni]);
#pragma unroll
            for (int mi = 0; mi < 2; mi++)
#pragma unroll
                for (int ni = 0; ni < 4; ni++) MMA_TF32(acc[mi][ni], alo[cur][mi], bhi[cur][ni]);
        }
        CP_WAIT0();
        __syncthreads();
    }

    // ---------- write logits to smem ----------
#pragma unroll
    for (int mi = 0; mi < 2; mi++)
#pragma unroll
        for (int ni = 0; ni < 4; ni++) {
            int row = warpM * 32 + mi * 16 + quad;
            int col = warpN * 32 + ni * 8 + 2 * qt;
            *(float2*)&Sf[row * LPAD + col]       = make_float2(acc[mi][ni][0], acc[mi][ni][1]);
            *(float2*)&Sf[(row + 8) * LPAD + col] = make_float2(acc[mi][ni][2], acc[mi][ni][3]);
        }
    __syncthreads();

    // ---------- per-token epilogue ----------
    const bool act = tid < BM;
    float v[E_EXP];
    float l1 = -1e30f, l2 = -1e30f, inv = 0.0f;
    int   i1 = 0, i2 = 0;
    if (act) {
        const float* row = &Sf[tid * LPAD];
#pragma unroll
        for (int j = 0; j < E_EXP / 4; j++) {
            float4 q = *(const float4*)&row[4 * j];
            v[4 * j] = q.x; v[4 * j + 1] = q.y; v[4 * j + 2] = q.z; v[4 * j + 3] = q.w;
        }
#pragma unroll
        for (int e = 0; e < E_EXP; e++) {
            float x = v[e];
            if (x > l1)      { l2 = l1; i2 = i1; l1 = x; i1 = e; }
            else if (x > l2) { l2 = x;  i2 = e; }
        }
        float ssum = 0.0f;
#pragma unroll
        for (int e = 0; e < E_EXP; e++) { float p = __expf(v[e] - l1); ssum += p; v[e] = p; }
        inv = 1.0f / ssum;
    }
    __syncthreads();
    if (act) {
#pragma unroll
        for (int j = 0; j < E_EXP / 4; j++) {
            float4 q = make_float4(v[4 * j] * inv, v[4 * j + 1] * inv, v[4 * j + 2] * inv, v[4 * j + 3] * inv);
            *(float4*)&Sf[tid * E_EXP + 4 * j] = q;
        }
        float e2 = __expf(l2 - l1);
        float dn = 1.0f / (1.0f + e2);
        int gm = m0 + tid;
        out[2 * gm + 0] = (float)i1;
        out[2 * gm + 1] = (float)i2;
        out[2 * T_TOK + 2 * gm + 0] = dn;
        out[2 * T_TOK + 2 * gm + 1] = e2 * dn;
        atomicAdd(&sCnt[i1], 1);
    }
    __syncthreads();

    // ---------- per-expert partials + fused aux reduction ----------
    if (tid < E_EXP) {
        float s = 0.0f;
#pragma unroll 8
        for (int m = 0; m < BM; m++) s += Sf[m * E_EXP + tid];
        g_psum[bid * E_EXP + tid] = s;
        g_pcnt[bid * E_EXP + tid] = (float)sCnt[tid];
    }
    __threadfence();
    __syncthreads();

    if (tid == 0) s_last = (atomicInc(&g_done, NCTA - 1) == NCTA - 1) ? 1u : 0u;
    __syncthreads();

    if (s_last) {
        __threadfence();
        if (tid < E_EXP) {
            float a = 0.0f, cn = 0.0f;
#pragma unroll 8
            for (int b = 0; b < NCTA; b++) {
                a  += __ldcg(&g_psum[b * E_EXP + tid]);
                cn += __ldcg(&g_pcnt[b * E_EXP + tid]);
            }
            float invT = 1.0f / (float)T_TOK;
            sRed[tid] = (cn * invT) * (a * invT);
        }
        __syncthreads();
        if (tid < 32) {
            float vv = sRed[tid] + sRed[tid + 32];
#pragma unroll
            for (int o = 16; o > 0; o >>= 1) vv += __shfl_xor_sync(0xFFFFFFFF, vv, o);
            if (tid == 0) out[4 * T_TOK] = (float)E_EXP * AUX_W * vv;
        }
    }
}

extern "C" void kernel_launch(void* const* d_in, const int* in_sizes, int n_in,
                              void* d_out, int out_size) {
    const float* X = (const float*)d_in[0];
    const float* W = (const float*)d_in[1];
    float* out = (float*)d_out;

    prep_kernel<<<128, 256>>>(W);
    cudaFuncSetAttribute(router_kernel, cudaFuncAttributeMaxDynamicSharedMemorySize, DYN_SMEM);
    router_kernel<<<NCTA, THREADS, DYN_SMEM>>>(X, W, out);
}